// round 2
// baseline (speedup 1.0000x reference)
#include <cuda_runtime.h>
#include <cuda_bf16.h>

// Problem constants (fixed-shape problem: 640000 edges, 100000 nodes, dims 128)
#define N_EDGES   640000
#define DIMV      128
#define TE        128          // edges per block
#define STRIDE    132          // smem row stride in floats (528B: 16B aligned, bank-skewed)
#define NTHREADS  256

// ---------------- packed f32x2 helpers (sm_103a dual-FMA path) ----------------
__device__ __forceinline__ unsigned long long dup2(float a) {
    unsigned long long r;
    asm("mov.b64 %0, {%1, %1};" : "=l"(r) : "f"(a));
    return r;
}
__device__ __forceinline__ void fma2(unsigned long long &d, unsigned long long a, unsigned long long b) {
    asm("fma.rn.f32x2 %0, %1, %2, %0;" : "+l"(d) : "l"(a), "l"(b));
}
__device__ __forceinline__ unsigned long long mul2(unsigned long long a, unsigned long long b) {
    unsigned long long r;
    asm("mul.rn.f32x2 %0, %1, %2;" : "=l"(r) : "l"(a), "l"(b));
    return r;
}
__device__ __forceinline__ unsigned long long add2(unsigned long long a, unsigned long long b) {
    unsigned long long r;
    asm("add.rn.f32x2 %0, %1, %2;" : "=l"(r) : "l"(a), "l"(b));
    return r;
}
__device__ __forceinline__ void unpack2(unsigned long long v, float &lo, float &hi) {
    asm("mov.b64 {%0, %1}, %2;" : "=f"(lo), "=f"(hi) : "l"(v));
}
__device__ __forceinline__ unsigned long long pack2(float lo, float hi) {
    unsigned long long r;
    asm("mov.b64 %0, {%1, %2};" : "=l"(r) : "f"(lo), "f"(hi));
    return r;
}

// ---------------- smem staging helpers ----------------

// Load a 128x128 weight tile W[o][k] (row-major, row stride `rowstride`, k offset `koff`)
// into smem k-major: sW[k*STRIDE + o]. Global reads fully coalesced (k contiguous).
__device__ __forceinline__ void load_w(const float* __restrict__ Wg, int rowstride, int koff,
                                       float* __restrict__ sW, int tid)
{
    #pragma unroll 8
    for (int r = 0; r < (128 * 128) / NTHREADS; ++r) {
        int idx = r * NTHREADS + tid;
        int o = idx >> 7;
        int k = idx & 127;
        sW[k * STRIDE + o] = Wg[o * rowstride + koff + k];
    }
}

// Gather TE rows of V (128 floats each) by index into sDst[e*STRIDE ...].
// One warp-chunk per row -> fully coalesced 512B row reads; conflict-free float4 smem stores.
__device__ __forceinline__ void gather_rows(const float* __restrict__ Vg, const int* __restrict__ idx,
                                            float* __restrict__ sDst, int tid)
{
    #pragma unroll
    for (int r = 0; r < (TE * 32) / NTHREADS; ++r) {
        int t = r * NTHREADS + tid;
        int e = t >> 5;          // row within tile
        int c = t & 31;          // float4 column
        int node = idx[e];
        float4 v = reinterpret_cast<const float4*>(Vg + (size_t)node * DIMV)[c];
        reinterpret_cast<float4*>(sDst + e * STRIDE)[c] = v;
    }
}

// Load TE contiguous rows of E with LeakyReLU(0.01) applied.
__device__ __forceinline__ void gather_E(const float* __restrict__ Eg, long e0,
                                         float* __restrict__ sDst, int tid)
{
    #pragma unroll
    for (int r = 0; r < (TE * 32) / NTHREADS; ++r) {
        int t = r * NTHREADS + tid;
        int e = t >> 5;
        int c = t & 31;
        float4 v = reinterpret_cast<const float4*>(Eg + (e0 + e) * DIMV)[c];
        v.x = v.x > 0.f ? v.x : 0.01f * v.x;
        v.y = v.y > 0.f ? v.y : 0.01f * v.y;
        v.z = v.z > 0.f ? v.z : 0.01f * v.z;
        v.w = v.w > 0.f ? v.w : 0.01f * v.w;
        reinterpret_cast<float4*>(sDst + e * STRIDE)[c] = v;
    }
}

// Register-tiled GEMM: OUT[e][o] += sum_k IN[e][k] * sW[k][o].
// Thread (ty,tx): e = i*16+ty (i<8), o = j*32+2*tx (+0/+1 packed) (j<4).
// Per k: 8 scalar IN loads (bank-clean: ty pair differs by STRIDE=132 -> bank+4),
//        4x 8B W loads (contiguous across tx), 32 packed FMAs (=64 MACs).
__device__ __forceinline__ void gemm128(const float* __restrict__ sIN, const float* __restrict__ sW,
                                        unsigned long long (&acc)[8][4], int ty, int tx)
{
    const float* pin = sIN + ty * STRIDE;
    const float* pw  = sW + 2 * tx;
    #pragma unroll 2
    for (int k = 0; k < 128; ++k) {
        unsigned long long a2[8];
        #pragma unroll
        for (int i = 0; i < 8; ++i) a2[i] = dup2(pin[i * 16 * STRIDE + k]);
        unsigned long long b2[4];
        #pragma unroll
        for (int j = 0; j < 4; ++j)
            b2[j] = *reinterpret_cast<const unsigned long long*>(pw + k * STRIDE + j * 32);
        #pragma unroll
        for (int i = 0; i < 8; ++i)
            #pragma unroll
            for (int j = 0; j < 4; ++j)
                fma2(acc[i][j], a2[i], b2[j]);
    }
}

__device__ __forceinline__ void zero_acc(unsigned long long (&acc)[8][4]) {
    #pragma unroll
    for (int i = 0; i < 8; ++i)
        #pragma unroll
        for (int j = 0; j < 4; ++j) acc[i][j] = 0ull;
}

// ---------------- fused kernel ----------------
// smem: sA (data tile 1), sB (data tile 2), sW (weight tile), each 128*132 floats.
#define SMEM_FLOATS (3 * TE * STRIDE)
#define SMEM_BYTES  (SMEM_FLOATS * sizeof(float))

__global__ void __launch_bounds__(NTHREADS, 1)
ecat_fused_kernel(const float* __restrict__ V, const float* __restrict__ E,
                  const int* __restrict__ src, const int* __restrict__ dst,
                  const float* __restrict__ U_w, const float* __restrict__ V_w,
                  const float* __restrict__ P_w, const float* __restrict__ P_b,
                  const float* __restrict__ W1, const float* __restrict__ b1,
                  const float* __restrict__ W2, const float* __restrict__ b2,
                  float* __restrict__ out)
{
    extern __shared__ float smem[];
    float* sA = smem;
    float* sB = smem + TE * STRIDE;
    float* sW = smem + 2 * TE * STRIDE;

    const int tid = threadIdx.x;
    const int tx = tid & 15;       // output-dim tile coordinate
    const int ty = tid >> 4;       // edge-dim tile coordinate
    const long e0 = (long)blockIdx.x * TE;

    unsigned long long acc[8][4];

    // ---- Stage 1: Hs = gather(V, src) @ U_w^T  -> stash in sB
    gather_rows(V, src + e0, sA, tid);
    load_w(U_w, 128, 0, sW, tid);
    __syncthreads();
    zero_acc(acc);
    gemm128(sA, sW, acc, ty, tx);
    #pragma unroll
    for (int i = 0; i < 8; ++i)
        #pragma unroll
        for (int j = 0; j < 4; ++j)
            *reinterpret_cast<unsigned long long*>(sB + (i * 16 + ty) * STRIDE + j * 32 + 2 * tx) = acc[i][j];
    __syncthreads();   // gemm reads of sA/sW complete before overwrite

    // ---- Stage 2: Hd = gather(V, dst) @ V_w^T ; t = tanh(Hs * Hd) -> sB
    gather_rows(V, dst + e0, sA, tid);
    load_w(V_w, 128, 0, sW, tid);
    __syncthreads();
    zero_acc(acc);
    gemm128(sA, sW, acc, ty, tx);
    #pragma unroll
    for (int i = 0; i < 8; ++i)
        #pragma unroll
        for (int j = 0; j < 4; ++j) {
            unsigned long long* p =
                reinterpret_cast<unsigned long long*>(sB + (i * 16 + ty) * STRIDE + j * 32 + 2 * tx);
            unsigned long long m = mul2(acc[i][j], *p);   // own coords: no cross-thread hazard
            float lo, hi;
            unpack2(m, lo, hi);
            *p = pack2(tanhf(lo), tanhf(hi));
        }
    __syncthreads();   // all of sB(t) written; sA/sW reads complete

    // ---- Stage 3: pooled = t @ P_w^T + P_b ; meanwhile stage LeakyReLU(E) into sA
    load_w(P_w, 128, 0, sW, tid);
    gather_E(E, e0, sA, tid);
    __syncthreads();
    zero_acc(acc);
    gemm128(sB, sW, acc, ty, tx);
    #pragma unroll
    for (int j = 0; j < 4; ++j) {
        unsigned long long pb =
            *reinterpret_cast<const unsigned long long*>(P_b + j * 32 + 2 * tx);
        #pragma unroll
        for (int i = 0; i < 8; ++i) acc[i][j] = add2(acc[i][j], pb);
    }
    __syncthreads();   // reads of sB/sW complete
    // pooled -> sB ; W1a -> sW
    #pragma unroll
    for (int i = 0; i < 8; ++i)
        #pragma unroll
        for (int j = 0; j < 4; ++j)
            *reinterpret_cast<unsigned long long*>(sB + (i * 16 + ty) * STRIDE + j * 32 + 2 * tx) = acc[i][j];
    load_w(W1, 256, 0, sW, tid);
    __syncthreads();

    // ---- Stage 4: y1 = relu(pooled @ W1a^T + Ea @ W1b^T + b1)
    unsigned long long accY[8][4];
    zero_acc(accY);
    gemm128(sB, sW, accY, ty, tx);
    __syncthreads();                 // sW reads complete
    load_w(W1, 256, 128, sW, tid);   // W1b
    __syncthreads();
    gemm128(sA, sW, accY, ty, tx);   // += Ea @ W1b^T
    #pragma unroll
    for (int j = 0; j < 4; ++j) {
        unsigned long long bb =
            *reinterpret_cast<const unsigned long long*>(b1 + j * 32 + 2 * tx);
        #pragma unroll
        for (int i = 0; i < 8; ++i) {
            unsigned long long s = add2(accY[i][j], bb);
            float lo, hi;
            unpack2(s, lo, hi);
            accY[i][j] = pack2(fmaxf(lo, 0.f), fmaxf(hi, 0.f));
        }
    }
    __syncthreads();   // reads of sA/sW complete
    // y1 -> sB ; W2 -> sW
    #pragma unroll
    for (int i = 0; i < 8; ++i)
        #pragma unroll
        for (int j = 0; j < 4; ++j)
            *reinterpret_cast<unsigned long long*>(sB + (i * 16 + ty) * STRIDE + j * 32 + 2 * tx) = accY[i][j];
    load_w(W2, 128, 0, sW, tid);
    __syncthreads();

    // ---- Stage 5: out = relu(y1 @ W2^T + b2)  (direct 64B-coalesced global stores)
    zero_acc(acc);
    gemm128(sB, sW, acc, ty, tx);
    #pragma unroll
    for (int i = 0; i < 8; ++i) {
        float* orow = out + (e0 + i * 16 + ty) * DIMV;
        #pragma unroll
        for (int j = 0; j < 4; ++j) {
            unsigned long long bb =
                *reinterpret_cast<const unsigned long long*>(b2 + j * 32 + 2 * tx);
            unsigned long long s = add2(acc[i][j], bb);
            float lo, hi;
            unpack2(s, lo, hi);
            float2 r;
            r.x = fmaxf(lo, 0.f);
            r.y = fmaxf(hi, 0.f);
            *reinterpret_cast<float2*>(orow + j * 32 + 2 * tx) = r;
        }
    }
}

extern "C" void kernel_launch(void* const* d_in, const int* in_sizes, int n_in,
                              void* d_out, int out_size)
{
    const float* V   = (const float*)d_in[0];
    const float* E   = (const float*)d_in[1];
    const int*   src = (const int*)d_in[2];
    const int*   dst = (const int*)d_in[3];
    const float* U_w = (const float*)d_in[4];
    const float* V_w = (const float*)d_in[5];
    const float* P_w = (const float*)d_in[6];
    const float* P_b = (const float*)d_in[7];
    const float* W1  = (const float*)d_in[8];
    const float* b1  = (const float*)d_in[9];
    const float* W2  = (const float*)d_in[10];
    const float* b2  = (const float*)d_in[11];
    float* out = (float*)d_out;

    int n_edges = in_sizes[2];          // src element count
    int blocks = n_edges / TE;          // 640000 / 128 = 5000 (exact)

    cudaFuncSetAttribute(ecat_fused_kernel,
                         cudaFuncAttributeMaxDynamicSharedMemorySize, SMEM_BYTES);
    ecat_fused_kernel<<<blocks, NTHREADS, SMEM_BYTES>>>(
        V, E, src, dst, U_w, V_w, P_w, P_b, W1, b1, W2, b2, out);
}

// round 4
// speedup vs baseline: 1.0959x; 1.0959x over previous
#include <cuda_runtime.h>
#include <cuda_bf16.h>
#include <cstdint>

#define NTH   256
#define TE    128
#define ST    136                       // bf16 elems per smem tile row (272B stride)
#define TILEB (128 * ST * 2)            // bytes per 128x128 bf16 tile = 34816
#define SMEM_BYTES (6 * TILEB)          // INh, INl, Xh, Xl, Wh, Wl = 208896 B

// ---------------- PTX helpers ----------------
__device__ __forceinline__ uint32_t smem_u32(const void* p) {
    uint32_t a;
    asm("{ .reg .u64 t; cvta.to.shared.u64 t, %1; cvt.u32.u64 %0, t; }" : "=r"(a) : "l"(p));
    return a;
}
#define LDSM4(r, addr)                                                              \
    asm volatile("ldmatrix.sync.aligned.m8n8.x4.shared.b16 {%0,%1,%2,%3}, [%4];"    \
                 : "=r"((r)[0]), "=r"((r)[1]), "=r"((r)[2]), "=r"((r)[3])           \
                 : "r"(addr))

__device__ __forceinline__ void mma_bf16(float* c, const uint32_t* a, uint32_t b0, uint32_t b1) {
    asm volatile("mma.sync.aligned.m16n8k16.row.col.f32.bf16.bf16.f32 "
                 "{%0,%1,%2,%3}, {%4,%5,%6,%7}, {%8,%9}, {%0,%1,%2,%3};"
                 : "+f"(c[0]), "+f"(c[1]), "+f"(c[2]), "+f"(c[3])
                 : "r"(a[0]), "r"(a[1]), "r"(a[2]), "r"(a[3]), "r"(b0), "r"(b1));
}

// ---------------- numeric helpers ----------------
__device__ __forceinline__ float bf16hi_rn(float a, uint32_t& hbits) {
    uint32_t u = __float_as_uint(a);
    uint32_t r = (u + 0x7FFFu + ((u >> 16) & 1u)) & 0xFFFF0000u;
    hbits = r;
    return __uint_as_float(r);
}
__device__ __forceinline__ uint32_t bf16x2_of(float lo, float hi) {
    uint32_t r;
    asm("cvt.rn.bf16x2.f32 %0, %1, %2;" : "=r"(r) : "f"(hi), "f"(lo));
    return r;
}
__device__ __forceinline__ float fast_tanh(float x) {
    float e = __expf(2.f * x);
    return 1.f - __fdividef(2.f, e + 1.f);
}
// store a (v0,v1) fp32 pair as bf16 hi/lo split at (row, col even)
__device__ __forceinline__ void stpair(char* Xh, char* Xl, int r, int c, float v0, float v1) {
    uint32_t h0b, h1b;
    float h0 = bf16hi_rn(v0, h0b), h1 = bf16hi_rn(v1, h1b);
    uint32_t off = (uint32_t)(r * ST + c) * 2;
    *reinterpret_cast<uint32_t*>(Xh + off) = __byte_perm(h0b, h1b, 0x7632);
    *reinterpret_cast<uint32_t*>(Xl + off) = bf16x2_of(v0 - h0, v1 - h1);
}

// ---------------- staging: fp32 global -> bf16 hi/lo smem tiles ----------------
// 2 threads per row; each converts 64 contiguous floats.
__device__ __forceinline__ void stage_row(const float* __restrict__ srcRow,
                                          char* __restrict__ Xh, char* __restrict__ Xl,
                                          int row, int half, bool leaky)
{
    const float4* s4 = reinterpret_cast<const float4*>(srcRow + half);
    uint32_t off0 = (uint32_t)(row * ST + half) * 2;
    #pragma unroll
    for (int i = 0; i < 16; ++i) {
        float4 t = s4[i];
        if (leaky) {
            t.x = t.x > 0.f ? t.x : 0.01f * t.x;
            t.y = t.y > 0.f ? t.y : 0.01f * t.y;
            t.z = t.z > 0.f ? t.z : 0.01f * t.z;
            t.w = t.w > 0.f ? t.w : 0.01f * t.w;
        }
        uint32_t r0, r1, r2, r3;
        float h0 = bf16hi_rn(t.x, r0), h1 = bf16hi_rn(t.y, r1);
        float h2 = bf16hi_rn(t.z, r2), h3 = bf16hi_rn(t.w, r3);
        uint2 hh = make_uint2(__byte_perm(r0, r1, 0x7632), __byte_perm(r2, r3, 0x7632));
        uint2 ll = make_uint2(bf16x2_of(t.x - h0, t.y - h1), bf16x2_of(t.z - h2, t.w - h3));
        *reinterpret_cast<uint2*>(Xh + off0 + i * 8) = hh;
        *reinterpret_cast<uint2*>(Xl + off0 + i * 8) = ll;
    }
}

__device__ __forceinline__ void gatherV(const float* __restrict__ Vg, const int* __restrict__ idx,
                                        char* Xh, char* Xl, int tid) {
    int row = tid >> 1, half = (tid & 1) << 6;
    stage_row(Vg + (size_t)idx[row] * 128, Xh, Xl, row, half, false);
}
__device__ __forceinline__ void gatherE(const float* __restrict__ Eg, long e0,
                                        char* Xh, char* Xl, int tid) {
    int row = tid >> 1, half = (tid & 1) << 6;
    stage_row(Eg + (e0 + row) * 128, Xh, Xl, row, half, true);
}
__device__ __forceinline__ void loadW(const float* __restrict__ Wg, int rs, int koff,
                                      char* Xh, char* Xl, int tid) {
    int row = tid >> 1, half = (tid & 1) << 6;
    stage_row(Wg + (size_t)row * rs + koff, Xh, Xl, row, half, false);
}

// ---------------- warp GEMM: 64x32 tile, 3-term bf16 split ----------------
// acc[f][nf][4] += A[m0+f*16 .. ][k] * W[n0+nf*8 .. ][k]
__device__ __forceinline__ void gemm3(uint32_t Ah, uint32_t Al, uint32_t Wh, uint32_t Wl,
                                      float (&acc)[4][4][4], int lane, int m0, int n0)
{
    const uint32_t offA = (uint32_t)((m0 + (lane & 15)) * ST + ((lane >> 4) << 3)) * 2;
    const uint32_t offB = (uint32_t)((n0 + (lane & 7) + (((lane >> 4) & 1) << 3)) * ST
                                     + (((lane >> 3) & 1) << 3)) * 2;
    #pragma unroll 1
    for (int ks = 0; ks < 8; ++ks) {
        uint32_t kb = (uint32_t)ks * 32;
        uint32_t ah[4][4], al[4][4], bh[2][4], bl[2][4];
        #pragma unroll
        for (int f = 0; f < 4; ++f) {
            LDSM4(ah[f], Ah + offA + f * (16 * ST * 2) + kb);
            LDSM4(al[f], Al + offA + f * (16 * ST * 2) + kb);
        }
        #pragma unroll
        for (int g = 0; g < 2; ++g) {
            LDSM4(bh[g], Wh + offB + g * (16 * ST * 2) + kb);
            LDSM4(bl[g], Wl + offB + g * (16 * ST * 2) + kb);
        }
        #pragma unroll
        for (int f = 0; f < 4; ++f)
            #pragma unroll
            for (int nf = 0; nf < 4; ++nf) {
                int g = nf >> 1, s = (nf & 1) * 2;
                mma_bf16(acc[f][nf], ah[f], bh[g][s], bh[g][s + 1]);   // Ah*Wh
                mma_bf16(acc[f][nf], ah[f], bl[g][s], bl[g][s + 1]);   // Ah*Wl
                mma_bf16(acc[f][nf], al[f], bh[g][s], bh[g][s + 1]);   // Al*Wh
            }
    }
}
#define ZACC(a)                                   \
    _Pragma("unroll") for (int _f = 0; _f < 4; ++_f) \
    _Pragma("unroll") for (int _n = 0; _n < 4; ++_n) \
    _Pragma("unroll") for (int _q = 0; _q < 4; ++_q) (a)[_f][_n][_q] = 0.f

// ---------------- kernel ----------------
__global__ void __launch_bounds__(NTH, 1)
ecat_hmma_kernel(const float* __restrict__ V, const float* __restrict__ E,
                 const int* __restrict__ src, const int* __restrict__ dst,
                 const float* __restrict__ U_w, const float* __restrict__ V_w,
                 const float* __restrict__ P_w, const float* __restrict__ P_b,
                 const float* __restrict__ W1, const float* __restrict__ b1,
                 const float* __restrict__ W2, const float* __restrict__ b2,
                 float* __restrict__ out)
{
    extern __shared__ char sm[];
    char* sINh = sm;
    char* sINl = sm + TILEB;
    char* sXh  = sm + 2 * TILEB;
    char* sXl  = sm + 3 * TILEB;
    char* sWh  = sm + 4 * TILEB;
    char* sWl  = sm + 5 * TILEB;
    const uint32_t uINh = smem_u32(sINh), uINl = smem_u32(sINl);
    const uint32_t uXh  = smem_u32(sXh),  uXl  = smem_u32(sXl);
    const uint32_t uWh  = smem_u32(sWh),  uWl  = smem_u32(sWl);

    const int tid = threadIdx.x;
    const int lane = tid & 31;
    const int w = tid >> 5;
    const int m0 = (w >> 2) * 64;            // warp row base
    const int n0 = (w & 3) * 32;             // warp col base
    const long e0 = (long)blockIdx.x * TE;

    const int rb = (lane >> 2);              // acc row-in-frag
    const int cb = (lane & 3) * 2;           // acc col-in-frag (even)

    // ---- Stage 1: Hs = gather(V,src) @ U_w^T (accS stays in regs) ----
    gatherV(V, src + e0, sINh, sINl, tid);
    loadW(U_w, 128, 0, sWh, sWl, tid);
    __syncthreads();
    float accS[4][4][4]; ZACC(accS);
    gemm3(uINh, uINl, uWh, uWl, accS, lane, m0, n0);
    __syncthreads();

    // ---- Stage 2: Hd = gather(V,dst) @ V_w^T ; t = tanh(Hs*Hd) -> sX ----
    gatherV(V, dst + e0, sINh, sINl, tid);
    loadW(V_w, 128, 0, sWh, sWl, tid);
    __syncthreads();
    float accD[4][4][4]; ZACC(accD);
    gemm3(uINh, uINl, uWh, uWl, accD, lane, m0, n0);
    #pragma unroll
    for (int f = 0; f < 4; ++f)
        #pragma unroll
        for (int nf = 0; nf < 4; ++nf) {
            int r = m0 + f * 16 + rb, c = n0 + nf * 8 + cb;
            stpair(sXh, sXl, r, c,
                   fast_tanh(accS[f][nf][0] * accD[f][nf][0]),
                   fast_tanh(accS[f][nf][1] * accD[f][nf][1]));
            stpair(sXh, sXl, r + 8, c,
                   fast_tanh(accS[f][nf][2] * accD[f][nf][2]),
                   fast_tanh(accS[f][nf][3] * accD[f][nf][3]));
        }
    __syncthreads();   // sIN/sW reads + sX writes complete

    // ---- Stage 3: pooled = t @ P_w^T + P_b ; stage Ea -> sIN ----
    gatherE(E, e0, sINh, sINl, tid);
    loadW(P_w, 128, 0, sWh, sWl, tid);
    __syncthreads();
    float accP[4][4][4]; ZACC(accP);
    gemm3(uXh, uXl, uWh, uWl, accP, lane, m0, n0);
    __syncthreads();   // sX/sW reads complete
    #pragma unroll
    for (int f = 0; f < 4; ++f)
        #pragma unroll
        for (int nf = 0; nf < 4; ++nf) {
            int r = m0 + f * 16 + rb, c = n0 + nf * 8 + cb;
            float2 pb = *reinterpret_cast<const float2*>(P_b + c);
            stpair(sXh, sXl, r, c, accP[f][nf][0] + pb.x, accP[f][nf][1] + pb.y);
            stpair(sXh, sXl, r + 8, c, accP[f][nf][2] + pb.x, accP[f][nf][3] + pb.y);
        }
    loadW(W1, 256, 0, sWh, sWl, tid);        // W1a
    __syncthreads();

    // ---- Stage 4: y1 = relu(pooled @ W1a^T + Ea @ W1b^T + b1) ----
    float accY[4][4][4]; ZACC(accY);
    gemm3(uXh, uXl, uWh, uWl, accY, lane, m0, n0);
    __syncthreads();   // sW reads complete
    loadW(W1, 256, 128, sWh, sWl, tid);      // W1b
    __syncthreads();
    gemm3(uINh, uINl, uWh, uWl, accY, lane, m0, n0);
    __syncthreads();   // sW/sIN reads complete (sX reads finished 2 syncs ago)
    #pragma unroll
    for (int f = 0; f < 4; ++f)
        #pragma unroll
        for (int nf = 0; nf < 4; ++nf) {
            int r = m0 + f * 16 + rb, c = n0 + nf * 8 + cb;
            float2 bb = *reinterpret_cast<const float2*>(b1 + c);
            stpair(sXh, sXl, r, c,
                   fmaxf(accY[f][nf][0] + bb.x, 0.f), fmaxf(accY[f][nf][1] + bb.y, 0.f));
            stpair(sXh, sXl, r + 8, c,
                   fmaxf(accY[f][nf][2] + bb.x, 0.f), fmaxf(accY[f][nf][3] + bb.y, 0.f));
        }
    loadW(W2, 128, 0, sWh, sWl, tid);
    __syncthreads();

    // ---- Stage 5: out = relu(y1 @ W2^T + b2) ----
    float accO[4][4][4]; ZACC(accO);
    gemm3(uXh, uXl, uWh, uWl, accO, lane, m0, n0);
    #pragma unroll
    for (int f = 0; f < 4; ++f)
        #pragma unroll
        for (int nf = 0; nf < 4; ++nf) {
            int r = m0 + f * 16 + rb, c = n0 + nf * 8 + cb;
            float2 bb = *reinterpret_cast<const float2*>(b2 + c);
            float2 o0, o1;
            o0.x = fmaxf(accO[f][nf][0] + bb.x, 0.f);
            o0.y = fmaxf(accO[f][nf][1] + bb.y, 0.f);
            o1.x = fmaxf(accO[f][nf][2] + bb.x, 0.f);
            o1.y = fmaxf(accO[f][nf][3] + bb.y, 0.f);
            *reinterpret_cast<float2*>(out + (e0 + r) * 128 + c) = o0;
            *reinterpret_cast<float2*>(out + (e0 + r + 8) * 128 + c) = o1;
        }
}

extern "C" void kernel_launch(void* const* d_in, const int* in_sizes, int n_in,
                              void* d_out, int out_size)
{
    const float* V   = (const float*)d_in[0];
    const float* E   = (const float*)d_in[1];
    const int*   src = (const int*)d_in[2];
    const int*   dst = (const int*)d_in[3];
    const float* U_w = (const float*)d_in[4];
    const float* V_w = (const float*)d_in[5];
    const float* P_w = (const float*)d_in[6];
    const float* P_b = (const float*)d_in[7];
    const float* W1  = (const float*)d_in[8];
    const float* b1  = (const float*)d_in[9];
    const float* W2  = (const float*)d_in[10];
    const float* b2  = (const float*)d_in[11];
    float* out = (float*)d_out;

    int n_edges = in_sizes[2];
    int blocks = n_edges / TE;   // 5000

    cudaFuncSetAttribute(ecat_hmma_kernel,
                         cudaFuncAttributeMaxDynamicSharedMemorySize, SMEM_BYTES);
    ecat_hmma_kernel<<<blocks, NTH, SMEM_BYTES>>>(
        V, E, src, dst, U_w, V_w, P_w, P_b, W1, b1, W2, b2, out);
}

// round 5
// speedup vs baseline: 2.3908x; 2.1816x over previous
#include <cuda_runtime.h>
#include <cuda_bf16.h>
#include <cstdint>

#define NTH     512
#define TE      128
#define ST      136                     // bf16 elems per smem tile row (272B)
#define TILEB   (128 * ST * 2)          // 34816 B per 128x128 bf16 tile
#define CHUNKS  (TILEB / 16)            // 2176 16B chunks
#define SMEM_BYTES  (6 * TILEB)         // edge kernel: IN(h,l) X(h,l) W(h,l)
#define NODE_SMEM   (4 * TILEB)         // node kernel: IN(h,l) W(h,l)
#define NODE_PAD 100096

// ---------------- device scratch (static allocation — allowed) ----------------
__device__ __align__(16) float gVU[(size_t)NODE_PAD * 128];
__device__ __align__(16) float gVV[(size_t)NODE_PAD * 128];
__device__ __align__(16) float gW1a[128 * 128];
__device__ __align__(16) float gB1p[128];
__device__ __align__(16) char  gWimg[3][2][TILEB];   // W1a', W1b, W2 as smem images

// ---------------- PTX helpers ----------------
__device__ __forceinline__ uint32_t smem_u32(const void* p) {
    uint32_t a;
    asm("{ .reg .u64 t; cvta.to.shared.u64 t, %1; cvt.u32.u64 %0, t; }" : "=r"(a) : "l"(p));
    return a;
}
#define LDSM4(r, addr)                                                              \
    asm volatile("ldmatrix.sync.aligned.m8n8.x4.shared.b16 {%0,%1,%2,%3}, [%4];"    \
                 : "=r"((r)[0]), "=r"((r)[1]), "=r"((r)[2]), "=r"((r)[3])           \
                 : "r"(addr))

__device__ __forceinline__ void mma_bf16(float* c, const uint32_t* a, uint32_t b0, uint32_t b1) {
    asm volatile("mma.sync.aligned.m16n8k16.row.col.f32.bf16.bf16.f32 "
                 "{%0,%1,%2,%3}, {%4,%5,%6,%7}, {%8,%9}, {%0,%1,%2,%3};"
                 : "+f"(c[0]), "+f"(c[1]), "+f"(c[2]), "+f"(c[3])
                 : "r"(a[0]), "r"(a[1]), "r"(a[2]), "r"(a[3]), "r"(b0), "r"(b1));
}
#define CP16(dst, src) \
    asm volatile("cp.async.ca.shared.global [%0], [%1], 16;" :: "r"(dst), "l"(src))
#define CP_COMMIT() asm volatile("cp.async.commit_group;" ::: "memory")
#define CP_WAIT()   asm volatile("cp.async.wait_group 0;" ::: "memory")

// ---------------- numeric helpers ----------------
__device__ __forceinline__ float bf16hi_rn(float a, uint32_t& hbits) {
    uint32_t u = __float_as_uint(a);
    uint32_t r = (u + 0x7FFFu + ((u >> 16) & 1u)) & 0xFFFF0000u;
    hbits = r;
    return __uint_as_float(r);
}
__device__ __forceinline__ uint32_t bf16x2_of(float lo, float hi) {
    uint32_t r;
    asm("cvt.rn.bf16x2.f32 %0, %1, %2;" : "=r"(r) : "f"(hi), "f"(lo));
    return r;
}
__device__ __forceinline__ float fast_tanh(float x) {
    float e = __expf(2.f * x);
    return 1.f - __fdividef(2.f, e + 1.f);
}
__device__ __forceinline__ void stpair(char* Xh, char* Xl, int r, int c, float v0, float v1) {
    uint32_t h0b, h1b;
    float h0 = bf16hi_rn(v0, h0b), h1 = bf16hi_rn(v1, h1b);
    uint32_t off = (uint32_t)(r * ST + c) * 2;
    *reinterpret_cast<uint32_t*>(Xh + off) = __byte_perm(h0b, h1b, 0x7632);
    *reinterpret_cast<uint32_t*>(Xl + off) = bf16x2_of(v0 - h0, v1 - h1);
}
// split 32 fp32 values -> hi/lo bf16x2, store 8B chunks at byte offset `off`
__device__ __forceinline__ void split_store32(const float* v, char* Xh, char* Xl, uint32_t off) {
    #pragma unroll
    for (int i = 0; i < 8; ++i) {
        float a = v[4*i], b = v[4*i+1], c = v[4*i+2], d = v[4*i+3];
        uint32_t r0, r1, r2, r3;
        float h0 = bf16hi_rn(a, r0), h1 = bf16hi_rn(b, r1);
        float h2 = bf16hi_rn(c, r2), h3 = bf16hi_rn(d, r3);
        uint2 hh = make_uint2(__byte_perm(r0, r1, 0x7632), __byte_perm(r2, r3, 0x7632));
        uint2 ll = make_uint2(bf16x2_of(a - h0, b - h1), bf16x2_of(c - h2, d - h3));
        *reinterpret_cast<uint2*>(Xh + off + i * 8) = hh;
        *reinterpret_cast<uint2*>(Xl + off + i * 8) = ll;
    }
}
// stage 32 contiguous fp32 (optionally leaky-relu) from global into hi/lo tiles
__device__ __forceinline__ void stage32(const float* __restrict__ src,
                                        char* Xh, char* Xl, uint32_t off, bool leaky) {
    float v[32];
    #pragma unroll
    for (int i = 0; i < 8; ++i) {
        float4 t = reinterpret_cast<const float4*>(src)[i];
        if (leaky) {
            t.x = t.x > 0.f ? t.x : 0.01f * t.x;
            t.y = t.y > 0.f ? t.y : 0.01f * t.y;
            t.z = t.z > 0.f ? t.z : 0.01f * t.z;
            t.w = t.w > 0.f ? t.w : 0.01f * t.w;
        }
        v[4*i] = t.x; v[4*i+1] = t.y; v[4*i+2] = t.z; v[4*i+3] = t.w;
    }
    split_store32(v, Xh, Xl, off);
}

// async-copy one preconverted weight tile pair into smem
__device__ __forceinline__ void cpasync_tile(uint32_t dH, uint32_t dL,
                                             const char* sH, const char* sL, int tid) {
    #pragma unroll
    for (int i = 0; i < 5; ++i) {
        int idx = i * NTH + tid;
        if (idx < CHUNKS) {
            CP16(dH + idx * 16, sH + idx * 16);
            CP16(dL + idx * 16, sL + idx * 16);
        }
    }
    CP_COMMIT();
}

// ---------------- warp GEMM: 32x32 tile, 3-term bf16 split ----------------
__device__ __forceinline__ void gemm3(uint32_t Ah, uint32_t Al, uint32_t Wh, uint32_t Wl,
                                      float (&acc)[2][4][4], int lane, int m0, int n0)
{
    const uint32_t offA = (uint32_t)((m0 + (lane & 15)) * ST + ((lane >> 4) << 3)) * 2;
    const uint32_t offB = (uint32_t)((n0 + (lane & 7) + (((lane >> 4) & 1) << 3)) * ST
                                     + (((lane >> 3) & 1) << 3)) * 2;
    #pragma unroll 1
    for (int ks = 0; ks < 8; ++ks) {
        uint32_t kb = (uint32_t)ks * 32;
        uint32_t ah[2][4], al[2][4], bh[2][4], bl[2][4];
        #pragma unroll
        for (int f = 0; f < 2; ++f) {
            LDSM4(ah[f], Ah + offA + f * (16 * ST * 2) + kb);
            LDSM4(al[f], Al + offA + f * (16 * ST * 2) + kb);
        }
        #pragma unroll
        for (int g = 0; g < 2; ++g) {
            LDSM4(bh[g], Wh + offB + g * (16 * ST * 2) + kb);
            LDSM4(bl[g], Wl + offB + g * (16 * ST * 2) + kb);
        }
        #pragma unroll
        for (int f = 0; f < 2; ++f)
            #pragma unroll
            for (int nf = 0; nf < 4; ++nf) {
                int g = nf >> 1, s = (nf & 1) * 2;
                mma_bf16(acc[f][nf], ah[f], bh[g][s], bh[g][s + 1]);
                mma_bf16(acc[f][nf], ah[f], bl[g][s], bl[g][s + 1]);
                mma_bf16(acc[f][nf], al[f], bh[g][s], bh[g][s + 1]);
            }
    }
}
#define ZACC(a)                                      \
    _Pragma("unroll") for (int _f = 0; _f < 2; ++_f) \
    _Pragma("unroll") for (int _n = 0; _n < 4; ++_n) \
    _Pragma("unroll") for (int _q = 0; _q < 4; ++_q) (a)[_f][_n][_q] = 0.f

// ================= prep kernel 1: W1a' = W1a @ P_w, b1' = b1 + W1a @ P_b =================
__global__ void __launch_bounds__(NTH, 1)
ecat_compose(const float* __restrict__ W1, const float* __restrict__ P_w,
             const float* __restrict__ P_b, const float* __restrict__ b1)
{
    int tid = threadIdx.x;
    int o = tid >> 2, jb = (tid & 3) * 32;
    float acc[32];
    #pragma unroll
    for (int j = 0; j < 32; ++j) acc[j] = 0.f;
    for (int i = 0; i < 128; ++i) {
        float w = W1[o * 256 + i];
        const float4* pr = reinterpret_cast<const float4*>(P_w + i * 128 + jb);
        #pragma unroll
        for (int j = 0; j < 8; ++j) {
            float4 p = pr[j];
            acc[4*j]   += w * p.x; acc[4*j+1] += w * p.y;
            acc[4*j+2] += w * p.z; acc[4*j+3] += w * p.w;
        }
    }
    #pragma unroll
    for (int j = 0; j < 8; ++j)
        reinterpret_cast<float4*>(gW1a + o * 128 + jb)[j] =
            make_float4(acc[4*j], acc[4*j+1], acc[4*j+2], acc[4*j+3]);
    if ((tid & 3) == 0) {
        float s = 0.f;
        for (int i = 0; i < 128; ++i) s += W1[o * 256 + i] * P_b[i];
        gB1p[o] = b1[o] + s;
    }
}

// ================= prep kernel 2: bf16 hi/lo smem-image conversion =================
__global__ void __launch_bounds__(NTH, 1)
ecat_convert(const float* __restrict__ W1, const float* __restrict__ W2)
{
    int b = blockIdx.x;
    int tid = threadIdx.x;
    int o = tid >> 2, qo = (tid & 3) * 32;
    const float* srcRow;
    if (b == 0)      srcRow = gW1a + o * 128 + qo;
    else if (b == 1) srcRow = W1 + o * 256 + 128 + qo;     // W1b
    else             srcRow = W2 + o * 128 + qo;
    stage32(srcRow, (char*)gWimg[b][0], (char*)gWimg[b][1],
            (uint32_t)(o * ST + qo) * 2, false);
}

// ================= prep kernel 3: VU = V@U_w^T, VV = V@V_w^T over nodes =================
__global__ void __launch_bounds__(NTH, 1)
ecat_node(const float* __restrict__ V, const float* __restrict__ U_w,
          const float* __restrict__ V_w, int n_nodes)
{
    extern __shared__ char sm[];
    char* sINh = sm;               char* sINl = sm + TILEB;
    char* sWh  = sm + 2 * TILEB;   char* sWl  = sm + 3 * TILEB;
    const uint32_t uINh = smem_u32(sINh), uINl = smem_u32(sINl);
    const uint32_t uWh  = smem_u32(sWh),  uWl  = smem_u32(sWl);

    const int tid = threadIdx.x, lane = tid & 31, w = tid >> 5;
    const int m0 = (w >> 2) * 32, n0 = (w & 3) * 32;
    const int rb = lane >> 2, cb = (lane & 3) * 2;
    const int r = tid >> 2, qo = (tid & 3) * 32;
    const int nb = blockIdx.x * 128;

    int n = nb + r;
    int nc = (n < n_nodes) ? n : 0;
    stage32(V + (size_t)nc * 128 + qo, sINh, sINl, (uint32_t)(r * ST + qo) * 2, false);
    stage32(U_w + (size_t)r * 128 + qo, sWh, sWl, (uint32_t)(r * ST + qo) * 2, false);
    __syncthreads();

    float acc[2][4][4]; ZACC(acc);
    gemm3(uINh, uINl, uWh, uWl, acc, lane, m0, n0);
    #pragma unroll
    for (int f = 0; f < 2; ++f)
        #pragma unroll
        for (int nf = 0; nf < 4; ++nf) {
            int rr = m0 + f * 16 + rb, c = n0 + nf * 8 + cb;
            if (nb + rr < n_nodes)
                *reinterpret_cast<float2*>(gVU + (size_t)(nb + rr) * 128 + c) =
                    make_float2(acc[f][nf][0], acc[f][nf][1]);
            if (nb + rr + 8 < n_nodes)
                *reinterpret_cast<float2*>(gVU + (size_t)(nb + rr + 8) * 128 + c) =
                    make_float2(acc[f][nf][2], acc[f][nf][3]);
        }
    __syncthreads();
    stage32(V_w + (size_t)r * 128 + qo, sWh, sWl, (uint32_t)(r * ST + qo) * 2, false);
    __syncthreads();

    ZACC(acc);
    gemm3(uINh, uINl, uWh, uWl, acc, lane, m0, n0);
    #pragma unroll
    for (int f = 0; f < 2; ++f)
        #pragma unroll
        for (int nf = 0; nf < 4; ++nf) {
            int rr = m0 + f * 16 + rb, c = n0 + nf * 8 + cb;
            if (nb + rr < n_nodes)
                *reinterpret_cast<float2*>(gVV + (size_t)(nb + rr) * 128 + c) =
                    make_float2(acc[f][nf][0], acc[f][nf][1]);
            if (nb + rr + 8 < n_nodes)
                *reinterpret_cast<float2*>(gVV + (size_t)(nb + rr + 8) * 128 + c) =
                    make_float2(acc[f][nf][2], acc[f][nf][3]);
        }
}

// ================= main edge kernel: 3 GEMM stages per 128-edge tile =================
__global__ void __launch_bounds__(NTH, 1)
ecat_edge(const float* __restrict__ E, const int* __restrict__ src,
          const int* __restrict__ dst, const float* __restrict__ b2,
          float* __restrict__ out)
{
    extern __shared__ char sm[];
    char* sINh = sm;               char* sINl = sm + TILEB;
    char* sXh  = sm + 2 * TILEB;   char* sXl  = sm + 3 * TILEB;
    char* sWh  = sm + 4 * TILEB;   char* sWl  = sm + 5 * TILEB;
    const uint32_t uINh = smem_u32(sINh), uINl = smem_u32(sINl);
    const uint32_t uXh  = smem_u32(sXh),  uXl  = smem_u32(sXl);
    const uint32_t uWh  = smem_u32(sWh),  uWl  = smem_u32(sWl);

    const int tid = threadIdx.x, lane = tid & 31, w = tid >> 5;
    const int m0 = (w >> 2) * 32, n0 = (w & 3) * 32;
    const int rb = lane >> 2, cb = (lane & 3) * 2;
    const int r = tid >> 2, qo = (tid & 3) * 32;
    const long e0 = (long)blockIdx.x * TE;

    // prefetch W1a' while gathering + tanh
    cpasync_tile(uWh, uWl, gWimg[0][0], gWimg[0][1], tid);
    {
        int s = src[e0 + r], d = dst[e0 + r];
        const float4* pu = reinterpret_cast<const float4*>(gVU + (size_t)s * 128 + qo);
        const float4* pv = reinterpret_cast<const float4*>(gVV + (size_t)d * 128 + qo);
        float v[32];
        #pragma unroll
        for (int i = 0; i < 8; ++i) {
            float4 a = pu[i], b = pv[i];
            v[4*i]   = fast_tanh(a.x * b.x);
            v[4*i+1] = fast_tanh(a.y * b.y);
            v[4*i+2] = fast_tanh(a.z * b.z);
            v[4*i+3] = fast_tanh(a.w * b.w);
        }
        split_store32(v, sXh, sXl, (uint32_t)(r * ST + qo) * 2);
    }
    CP_WAIT();
    __syncthreads();

    // ---- GEMM 1: acc = t @ W1a'^T ----
    float acc[2][4][4]; ZACC(acc);
    gemm3(uXh, uXl, uWh, uWl, acc, lane, m0, n0);
    __syncthreads();                     // sW (and sX) reads complete

    // ---- stage Ea -> sIN ; prefetch W1b ----
    cpasync_tile(uWh, uWl, gWimg[1][0], gWimg[1][1], tid);
    stage32(E + (e0 + r) * 128 + qo, sINh, sINl, (uint32_t)(r * ST + qo) * 2, true);
    CP_WAIT();
    __syncthreads();

    // ---- GEMM 2: acc += Ea @ W1b^T ; y1 = relu(acc + b1') -> sX ----
    gemm3(uINh, uINl, uWh, uWl, acc, lane, m0, n0);
    #pragma unroll
    for (int f = 0; f < 2; ++f)
        #pragma unroll
        for (int nf = 0; nf < 4; ++nf) {
            int rr = m0 + f * 16 + rb, c = n0 + nf * 8 + cb;
            float2 bb = *reinterpret_cast<const float2*>(gB1p + c);
            stpair(sXh, sXl, rr, c,
                   fmaxf(acc[f][nf][0] + bb.x, 0.f), fmaxf(acc[f][nf][1] + bb.y, 0.f));
            stpair(sXh, sXl, rr + 8, c,
                   fmaxf(acc[f][nf][2] + bb.x, 0.f), fmaxf(acc[f][nf][3] + bb.y, 0.f));
        }
    __syncthreads();                     // gemm2 reads + y1 writes complete
    cpasync_tile(uWh, uWl, gWimg[2][0], gWimg[2][1], tid);
    CP_WAIT();
    __syncthreads();

    // ---- GEMM 3: out = relu(y1 @ W2^T + b2) ----
    ZACC(acc);
    gemm3(uXh, uXl, uWh, uWl, acc, lane, m0, n0);
    #pragma unroll
    for (int f = 0; f < 2; ++f)
        #pragma unroll
        for (int nf = 0; nf < 4; ++nf) {
            int rr = m0 + f * 16 + rb, c = n0 + nf * 8 + cb;
            float2 bb = *reinterpret_cast<const float2*>(b2 + c);
            *reinterpret_cast<float2*>(out + (e0 + rr) * 128 + c) =
                make_float2(fmaxf(acc[f][nf][0] + bb.x, 0.f), fmaxf(acc[f][nf][1] + bb.y, 0.f));
            *reinterpret_cast<float2*>(out + (e0 + rr + 8) * 128 + c) =
                make_float2(fmaxf(acc[f][nf][2] + bb.x, 0.f), fmaxf(acc[f][nf][3] + bb.y, 0.f));
        }
}

// ================= host =================
extern "C" void kernel_launch(void* const* d_in, const int* in_sizes, int n_in,
                              void* d_out, int out_size)
{
    const float* V   = (const float*)d_in[0];
    const float* E   = (const float*)d_in[1];
    const int*   src = (const int*)d_in[2];
    const int*   dst = (const int*)d_in[3];
    const float* U_w = (const float*)d_in[4];
    const float* V_w = (const float*)d_in[5];
    const float* P_w = (const float*)d_in[6];
    const float* P_b = (const float*)d_in[7];
    const float* W1  = (const float*)d_in[8];
    const float* b1  = (const float*)d_in[9];
    const float* W2  = (const float*)d_in[10];
    const float* b2  = (const float*)d_in[11];
    float* out = (float*)d_out;

    int n_nodes = in_sizes[0] / 128;
    int n_edges = in_sizes[2];
    int node_blocks = (n_nodes + 127) / 128;
    int edge_blocks = n_edges / TE;

    static bool attr_set = false;
    if (!attr_set) {
        cudaFuncSetAttribute(ecat_node, cudaFuncAttributeMaxDynamicSharedMemorySize, NODE_SMEM);
        cudaFuncSetAttribute(ecat_edge, cudaFuncAttributeMaxDynamicSharedMemorySize, SMEM_BYTES);
        attr_set = true;
    }

    ecat_compose<<<1, NTH>>>(W1, P_w, P_b, b1);
    ecat_convert<<<3, NTH>>>(W1, W2);
    ecat_node<<<node_blocks, NTH, NODE_SMEM>>>(V, U_w, V_w, n_nodes);
    ecat_edge<<<edge_blocks, NTH, SMEM_BYTES>>>(E, src, dst, b2, out);
}

// round 7
// speedup vs baseline: 4.0550x; 1.6961x over previous
#include <cuda_runtime.h>
#include <cuda_bf16.h>
#include <cstdint>

#define NTH   512
#define ST    136                        // bf16 per weight-tile row (272 B stride)
#define TILEB (128 * ST * 2)             // 34816 B per 128x128 bf16 tile
#define EDGE_SMEM (6 * TILEB)            // W1a'(h,l) W1b(h,l) W2(h,l) = 208896
#define NODE_SMEM (4 * TILEB)            // U(h,l) V(h,l) = 139264
#define NODE_PAD 100096

// ---------------- device scratch (static, allowed) ----------------
__device__ __align__(16) float gVU[(size_t)NODE_PAD * 128];
__device__ __align__(16) float gVV[(size_t)NODE_PAD * 128];
__device__ __align__(16) float gW1a[128 * 128];
__device__ __align__(16) float gB1p[128];
__device__ __align__(16) char  gWimg[5][2][TILEB];  // 0:W1a' 1:W1b 2:W2 3:U_w 4:V_w

// ---------------- PTX helpers ----------------
__device__ __forceinline__ uint32_t smem_u32(const void* p) {
    uint32_t a;
    asm("{ .reg .u64 t; cvta.to.shared.u64 t, %1; cvt.u32.u64 %0, t; }" : "=r"(a) : "l"(p));
    return a;
}
#define LDSM4(r, addr)                                                              \
    asm volatile("ldmatrix.sync.aligned.m8n8.x4.shared.b16 {%0,%1,%2,%3}, [%4];"    \
                 : "=r"((r)[0]), "=r"((r)[1]), "=r"((r)[2]), "=r"((r)[3])           \
                 : "r"(addr))
__device__ __forceinline__ void mma_bf16(float* c, const uint32_t* a, uint32_t b0, uint32_t b1) {
    asm volatile("mma.sync.aligned.m16n8k16.row.col.f32.bf16.bf16.f32 "
                 "{%0,%1,%2,%3}, {%4,%5,%6,%7}, {%8,%9}, {%0,%1,%2,%3};"
                 : "+f"(c[0]), "+f"(c[1]), "+f"(c[2]), "+f"(c[3])
                 : "r"(a[0]), "r"(a[1]), "r"(a[2]), "r"(a[3]), "r"(b0), "r"(b1));
}
#define CP16(dst, src) \
    asm volatile("cp.async.ca.shared.global [%0], [%1], 16;" :: "r"(dst), "l"(src))
#define CP_COMMIT() asm volatile("cp.async.commit_group;" ::: "memory")
#define CP_WAIT()   asm volatile("cp.async.wait_group 0;" ::: "memory")

// ---------------- numeric helpers ----------------
__device__ __forceinline__ float bf16hi_rn(float a, uint32_t& hbits) {
    uint32_t u = __float_as_uint(a);
    uint32_t r = (u + 0x7FFFu + ((u >> 16) & 1u)) & 0xFFFF0000u;
    hbits = r;
    return __uint_as_float(r);
}
__device__ __forceinline__ uint32_t bf16x2_of(float lo, float hi) {
    uint32_t r;
    asm("cvt.rn.bf16x2.f32 %0, %1, %2;" : "=r"(r) : "f"(hi), "f"(lo));
    return r;
}
__device__ __forceinline__ void split2(float x, float y, uint32_t& h, uint32_t& l) {
    uint32_t rx, ry;
    float hx = bf16hi_rn(x, rx), hy = bf16hi_rn(y, ry);
    h = __byte_perm(rx, ry, 0x7632);
    l = bf16x2_of(x - hx, y - hy);
}
__device__ __forceinline__ float fast_tanh(float x) {
    float e = __expf(2.f * x);
    return 1.f - __fdividef(2.f, e + 1.f);
}
__device__ __forceinline__ float lk(float v) { return v > 0.f ? v : 0.01f * v; }

// stage 32 contiguous fp32 from global into hi/lo bf16 tiles (convert kernel)
__device__ __forceinline__ void stage32(const float* __restrict__ src,
                                        char* Xh, char* Xl, uint32_t off) {
    #pragma unroll
    for (int i = 0; i < 8; ++i) {
        float4 t = reinterpret_cast<const float4*>(src)[i];
        uint32_t r0, r1, r2, r3;
        float h0 = bf16hi_rn(t.x, r0), h1 = bf16hi_rn(t.y, r1);
        float h2 = bf16hi_rn(t.z, r2), h3 = bf16hi_rn(t.w, r3);
        uint2 hh = make_uint2(__byte_perm(r0, r1, 0x7632), __byte_perm(r2, r3, 0x7632));
        uint2 ll = make_uint2(bf16x2_of(t.x - h0, t.y - h1), bf16x2_of(t.z - h2, t.w - h3));
        *reinterpret_cast<uint2*>(Xh + off + i * 8) = hh;
        *reinterpret_cast<uint2*>(Xl + off + i * 8) = ll;
    }
}

// ---------------- core: A-in-registers 3-term GEMM step over n-groups ----------------
// baseH/baseL already include offB + ks*32. Group g covers n-frags 2g, 2g+1.
__device__ __forceinline__ void gemm_groups(float* acc, const uint32_t* ah, const uint32_t* al,
                                            uint32_t baseH, uint32_t baseL, int ngroups)
{
    #pragma unroll
    for (int g = 0; g < 8; ++g) {
        if (g >= ngroups) break;
        uint32_t bh[4], bl[4];
        LDSM4(bh, baseH + g * (16 * ST * 2));
        LDSM4(bl, baseL + g * (16 * ST * 2));
        mma_bf16(acc + 8 * g,     ah, bh[0], bh[1]);
        mma_bf16(acc + 8 * g,     ah, bl[0], bl[1]);
        mma_bf16(acc + 8 * g,     al, bh[0], bh[1]);
        mma_bf16(acc + 8 * g + 4, ah, bh[2], bh[3]);
        mma_bf16(acc + 8 * g + 4, ah, bl[2], bl[3]);
        mma_bf16(acc + 8 * g + 4, al, bh[2], bh[3]);
    }
}

// ================= prep 1: W1a' = W1a @ P_w, b1' = b1 + W1a @ P_b =================
__global__ void __launch_bounds__(NTH, 1)
ecat_compose(const float* __restrict__ W1, const float* __restrict__ P_w,
             const float* __restrict__ P_b, const float* __restrict__ b1)
{
    int tid = threadIdx.x;
    int o = tid >> 2, jb = (tid & 3) * 32;
    float acc[32];
    #pragma unroll
    for (int j = 0; j < 32; ++j) acc[j] = 0.f;
    for (int i = 0; i < 128; ++i) {
        float w = W1[o * 256 + i];
        const float4* pr = reinterpret_cast<const float4*>(P_w + i * 128 + jb);
        #pragma unroll
        for (int j = 0; j < 8; ++j) {
            float4 p = pr[j];
            acc[4*j]   += w * p.x; acc[4*j+1] += w * p.y;
            acc[4*j+2] += w * p.z; acc[4*j+3] += w * p.w;
        }
    }
    #pragma unroll
    for (int j = 0; j < 8; ++j)
        reinterpret_cast<float4*>(gW1a + o * 128 + jb)[j] =
            make_float4(acc[4*j], acc[4*j+1], acc[4*j+2], acc[4*j+3]);
    if ((tid & 3) == 0) {
        float s = 0.f;
        for (int i = 0; i < 128; ++i) s += W1[o * 256 + i] * P_b[i];
        gB1p[o] = b1[o] + s;
    }
}

// ================= prep 2: weight tiles -> bf16 hi/lo smem images =================
__global__ void __launch_bounds__(NTH, 1)
ecat_convert(const float* __restrict__ W1, const float* __restrict__ W2,
             const float* __restrict__ U_w, const float* __restrict__ V_w)
{
    int b = blockIdx.x;
    int tid = threadIdx.x;
    int o = tid >> 2, qo = (tid & 3) * 32;
    const float* srcRow;
    if (b == 0)      srcRow = gW1a + o * 128 + qo;
    else if (b == 1) srcRow = W1 + o * 256 + 128 + qo;
    else if (b == 2) srcRow = W2 + o * 128 + qo;
    else if (b == 3) srcRow = U_w + (size_t)o * 128 + qo;
    else             srcRow = V_w + (size_t)o * 128 + qo;
    stage32(srcRow, (char*)gWimg[b][0], (char*)gWimg[b][1], (uint32_t)(o * ST + qo) * 2);
}

// ================= prep 3: VU = V@U_w^T, VV = V@V_w^T (A-in-regs) =================
__global__ void __launch_bounds__(NTH, 1)
ecat_node(const float* __restrict__ V, int n_nodes)
{
    extern __shared__ char sm[];
    uint32_t smb = smem_u32(sm);
    const char* gsrc = &gWimg[3][0][0];
    #pragma unroll
    for (int i = 0; i < 17; ++i) {
        int idx = i * NTH + threadIdx.x;
        CP16(smb + idx * 16, gsrc + idx * 16);   // 17*512 = 8704 chunks exactly
    }
    CP_COMMIT(); CP_WAIT();
    __syncthreads();

    const int tid = threadIdx.x, lane = tid & 31, w = tid >> 5;
    const int r0 = lane >> 2, il = lane & 3, cb = il * 2;
    const uint32_t offB = (uint32_t)(((lane & 7) + (((lane >> 4) & 1) << 3)) * ST
                                     + (((lane >> 3) & 1) << 3)) * 2;
    int n0 = blockIdx.x * 256 + w * 16 + r0;
    int n1 = n0 + 8;
    int n0c = n0 < n_nodes ? n0 : 0;
    int n1c = n1 < n_nodes ? n1 : 0;
    const float2* pa0 = reinterpret_cast<const float2*>(V + (size_t)n0c * 128);
    const float2* pa1 = reinterpret_cast<const float2*>(V + (size_t)n1c * 128);

    #pragma unroll 1
    for (int pass = 0; pass < 2; ++pass) {
        uint32_t bH = smb + pass * 2 * TILEB, bL = bH + TILEB;
        float acc[64];
        #pragma unroll
        for (int i = 0; i < 64; ++i) acc[i] = 0.f;
        #pragma unroll 1
        for (int ks = 0; ks < 8; ++ks) {
            int i0 = il + 8 * ks, i1 = i0 + 4;
            float2 a00 = pa0[i0], a01 = pa0[i1], a10 = pa1[i0], a11 = pa1[i1];
            uint32_t ah[4], al[4];
            split2(a00.x, a00.y, ah[0], al[0]);
            split2(a10.x, a10.y, ah[1], al[1]);
            split2(a01.x, a01.y, ah[2], al[2]);
            split2(a11.x, a11.y, ah[3], al[3]);
            gemm_groups(acc, ah, al, bH + offB + ks * 32, bL + offB + ks * 32, 8);
        }
        float* dstb = pass ? gVV : gVU;
        #pragma unroll
        for (int nf = 0; nf < 16; ++nf) {
            int c = nf * 8 + cb;
            if (n0 < n_nodes)
                *reinterpret_cast<float2*>(dstb + (size_t)n0 * 128 + c) =
                    make_float2(acc[nf*4], acc[nf*4+1]);
            if (n1 < n_nodes)
                *reinterpret_cast<float2*>(dstb + (size_t)n1 * 128 + c) =
                    make_float2(acc[nf*4+2], acc[nf*4+3]);
        }
    }
}

// ================= main edge kernel: persistent, barrier-free mainloop =================
__global__ void __launch_bounds__(NTH, 1)
ecat_edge(const float* __restrict__ E, const int* __restrict__ src,
          const int* __restrict__ dst, const float* __restrict__ b2,
          float* __restrict__ out, int n_tiles)
{
    extern __shared__ char sm[];
    uint32_t smb = smem_u32(sm);
    const char* gsrc = &gWimg[0][0][0];
    #pragma unroll
    for (int i = 0; i < 26; ++i) {
        int idx = i * NTH + threadIdx.x;
        if (idx < 6 * TILEB / 16) CP16(smb + idx * 16, gsrc + idx * 16);
    }
    CP_COMMIT(); CP_WAIT();
    __syncthreads();

    const int tid = threadIdx.x, lane = tid & 31, w = tid >> 5;
    const int r0 = lane >> 2, il = lane & 3, cb = il * 2;
    const uint32_t offB = (uint32_t)(((lane & 7) + (((lane >> 4) & 1) << 3)) * ST
                                     + (((lane >> 3) & 1) << 3)) * 2;
    const uint32_t uW1aH = smb,             uW1aL = smb + TILEB;
    const uint32_t uW1bH = smb + 2 * TILEB, uW1bL = smb + 3 * TILEB;
    const uint32_t uW2H  = smb + 4 * TILEB, uW2L  = smb + 5 * TILEB;

    for (int t = blockIdx.x; t < n_tiles; t += gridDim.x) {
        long er0 = (long)t * 256 + w * 16 + r0;
        long er1 = er0 + 8;
        int s0 = __ldg(src + er0), s1 = __ldg(src + er1);
        int d0 = __ldg(dst + er0), d1 = __ldg(dst + er1);
        const float2* pu0 = reinterpret_cast<const float2*>(gVU + (size_t)s0 * 128);
        const float2* pu1 = reinterpret_cast<const float2*>(gVU + (size_t)s1 * 128);
        const float2* pv0 = reinterpret_cast<const float2*>(gVV + (size_t)d0 * 128);
        const float2* pv1 = reinterpret_cast<const float2*>(gVV + (size_t)d1 * 128);
        const float2* pe0 = reinterpret_cast<const float2*>(E + er0 * 128);
        const float2* pe1 = reinterpret_cast<const float2*>(E + er1 * 128);

        float acc[64];
        #pragma unroll
        for (int i = 0; i < 64; ++i) acc[i] = 0.f;

        // ---- GEMM A: t = tanh(VU[src] * VV[dst]) @ W1a'^T (A streamed in regs) ----
        #pragma unroll 1
        for (int ks = 0; ks < 8; ++ks) {
            int i0 = il + 8 * ks, i1 = i0 + 4;
            float2 u00 = pu0[i0], u01 = pu0[i1], u10 = pu1[i0], u11 = pu1[i1];
            float2 v00 = pv0[i0], v01 = pv0[i1], v10 = pv1[i0], v11 = pv1[i1];
            uint32_t ah[4], al[4];
            split2(fast_tanh(u00.x * v00.x), fast_tanh(u00.y * v00.y), ah[0], al[0]);
            split2(fast_tanh(u10.x * v10.x), fast_tanh(u10.y * v10.y), ah[1], al[1]);
            split2(fast_tanh(u01.x * v01.x), fast_tanh(u01.y * v01.y), ah[2], al[2]);
            split2(fast_tanh(u11.x * v11.x), fast_tanh(u11.y * v11.y), ah[3], al[3]);
            gemm_groups(acc, ah, al, uW1aH + offB + ks * 32, uW1aL + offB + ks * 32, 8);
        }
        // ---- GEMM B: acc += leaky(E) @ W1b^T (A streamed in regs) ----
        #pragma unroll 1
        for (int ks = 0; ks < 8; ++ks) {
            int i0 = il + 8 * ks, i1 = i0 + 4;
            float2 e00 = pe0[i0], e01 = pe0[i1], e10 = pe1[i0], e11 = pe1[i1];
            uint32_t ah[4], al[4];
            split2(lk(e00.x), lk(e00.y), ah[0], al[0]);
            split2(lk(e10.x), lk(e10.y), ah[1], al[1]);
            split2(lk(e01.x), lk(e01.y), ah[2], al[2]);
            split2(lk(e11.x), lk(e11.y), ah[3], al[3]);
            gemm_groups(acc, ah, al, uW1bH + offB + ks * 32, uW1bL + offB + ks * 32, 8);
        }
        // ---- y1 = relu(acc + b1'): repack C-frags directly into GEMM-3 A-frags ----
        uint32_t yh[8][4], yl[8][4];
        #pragma unroll
        for (int ks = 0; ks < 8; ++ks) {
            #pragma unroll
            for (int p = 0; p < 2; ++p) {
                int nf = 2 * ks + p;
                float2 bb = __ldg(reinterpret_cast<const float2*>(gB1p + nf * 8 + cb));
                float y0 = fmaxf(acc[nf*4+0] + bb.x, 0.f);
                float y1v = fmaxf(acc[nf*4+1] + bb.y, 0.f);
                float y2 = fmaxf(acc[nf*4+2] + bb.x, 0.f);
                float y3 = fmaxf(acc[nf*4+3] + bb.y, 0.f);
                split2(y0, y1v, yh[ks][2*p],     yl[ks][2*p]);
                split2(y2, y3,  yh[ks][2*p + 1], yl[ks][2*p + 1]);
            }
        }
        // ---- GEMM C: out = relu(y1 @ W2^T + b2), n processed in halves ----
        #pragma unroll 1
        for (int h = 0; h < 2; ++h) {
            float acc2[32];
            #pragma unroll
            for (int i = 0; i < 32; ++i) acc2[i] = 0.f;
            uint32_t hb = (uint32_t)h * (64 * ST * 2);
            #pragma unroll 1
            for (int ks = 0; ks < 8; ++ks)
                gemm_groups(acc2, yh[ks], yl[ks],
                            uW2H + offB + hb + ks * 32, uW2L + offB + hb + ks * 32, 4);
            #pragma unroll
            for (int nf = 0; nf < 8; ++nf) {
                int c = h * 64 + nf * 8 + cb;
                float2 bb = __ldg(reinterpret_cast<const float2*>(b2 + c));
                *reinterpret_cast<float2*>(out + er0 * 128 + c) =
                    make_float2(fmaxf(acc2[nf*4+0] + bb.x, 0.f),
                                fmaxf(acc2[nf*4+1] + bb.y, 0.f));
                *reinterpret_cast<float2*>(out + er1 * 128 + c) =
                    make_float2(fmaxf(acc2[nf*4+2] + bb.x, 0.f),
                                fmaxf(acc2[nf*4+3] + bb.y, 0.f));
            }
        }
    }
}

// ================= host =================
extern "C" void kernel_launch(void* const* d_in, const int* in_sizes, int n_in,
                              void* d_out, int out_size)
{
    const float* V   = (const float*)d_in[0];
    const float* E   = (const float*)d_in[1];
    const int*   src = (const int*)d_in[2];
    const int*   dst = (const int*)d_in[3];
    const float* U_w = (const float*)d_in[4];
    const float* V_w = (const float*)d_in[5];
    const float* P_w = (const float*)d_in[6];
    const float* P_b = (const float*)d_in[7];
    const float* W1  = (const float*)d_in[8];
    const float* b1  = (const float*)d_in[9];
    const float* W2  = (const float*)d_in[10];
    const float* b2  = (const float*)d_in[11];
    float* out = (float*)d_out;

    int n_nodes = in_sizes[0] / 128;
    int n_edges = in_sizes[2];
    int n_tiles = n_edges / 256;                 // 2500
    int node_blocks = (n_nodes + 255) / 256;     // 391

    static int sms = 0;
    if (!sms) {
        cudaDeviceGetAttribute(&sms, cudaDevAttrMultiProcessorCount, 0);
        cudaFuncSetAttribute(ecat_node, cudaFuncAttributeMaxDynamicSharedMemorySize, NODE_SMEM);
        cudaFuncSetAttribute(ecat_edge, cudaFuncAttributeMaxDynamicSharedMemorySize, EDGE_SMEM);
    }

    ecat_compose<<<1, NTH>>>(W1, P_w, P_b, b1);
    ecat_convert<<<5, NTH>>>(W1, W2, U_w, V_w);
    ecat_node<<<node_blocks, NTH, NODE_SMEM>>>(V, n_nodes);
    ecat_edge<<<sms, NTH, EDGE_SMEM>>>(E, src, dst, b2, out, n_tiles);
}

// round 8
// speedup vs baseline: 4.0637x; 1.0022x over previous
#include <cuda_runtime.h>
#include <cuda_bf16.h>
#include <cstdint>

#define NTH   512
#define ST    136                        // bf16 per weight-tile row (272 B stride)
#define TILEB (128 * ST * 2)             // 34816 B per 128x128 bf16 tile
#define EDGE_SMEM (6 * TILEB)            // W1a'(h,l) W1b(h,l) W2(h,l) = 208896
#define NODE_SMEM (4 * TILEB)            // U(h,l) V(h,l) = 139264
#define NODE_PAD 100096

// ---------------- device scratch (static, allowed) ----------------
__device__ __align__(16) float gVU[(size_t)NODE_PAD * 128];
__device__ __align__(16) float gVV[(size_t)NODE_PAD * 128];
__device__ __align__(16) float gW1a[128 * 128];
__device__ __align__(16) float gB1p[128];
__device__ __align__(16) char  gWimg[5][2][TILEB];  // 0:W1a' 1:W1b 2:W2 3:U_w 4:V_w

// ---------------- PTX helpers ----------------
__device__ __forceinline__ uint32_t smem_u32(const void* p) {
    uint32_t a;
    asm("{ .reg .u64 t; cvta.to.shared.u64 t, %1; cvt.u32.u64 %0, t; }" : "=r"(a) : "l"(p));
    return a;
}
#define LDSM4(r, addr)                                                              \
    asm volatile("ldmatrix.sync.aligned.m8n8.x4.shared.b16 {%0,%1,%2,%3}, [%4];"    \
                 : "=r"((r)[0]), "=r"((r)[1]), "=r"((r)[2]), "=r"((r)[3])           \
                 : "r"(addr))
__device__ __forceinline__ void mma_bf16(float* c, const uint32_t* a, uint32_t b0, uint32_t b1) {
    asm volatile("mma.sync.aligned.m16n8k16.row.col.f32.bf16.bf16.f32 "
                 "{%0,%1,%2,%3}, {%4,%5,%6,%7}, {%8,%9}, {%0,%1,%2,%3};"
                 : "+f"(c[0]), "+f"(c[1]), "+f"(c[2]), "+f"(c[3])
                 : "r"(a[0]), "r"(a[1]), "r"(a[2]), "r"(a[3]), "r"(b0), "r"(b1));
}
#define CP16(dst, src) \
    asm volatile("cp.async.ca.shared.global [%0], [%1], 16;" :: "r"(dst), "l"(src))
#define CP_COMMIT() asm volatile("cp.async.commit_group;" ::: "memory")
#define CP_WAIT()   asm volatile("cp.async.wait_group 0;" ::: "memory")

// ---------------- numeric helpers ----------------
__device__ __forceinline__ float bf16hi_rn(float a, uint32_t& hbits) {
    uint32_t u = __float_as_uint(a);
    uint32_t r = (u + 0x7FFFu + ((u >> 16) & 1u)) & 0xFFFF0000u;
    hbits = r;
    return __uint_as_float(r);
}
__device__ __forceinline__ uint32_t bf16x2_of(float lo, float hi) {
    uint32_t r;
    asm("cvt.rn.bf16x2.f32 %0, %1, %2;" : "=r"(r) : "f"(hi), "f"(lo));
    return r;
}
__device__ __forceinline__ void split2(float x, float y, uint32_t& h, uint32_t& l) {
    uint32_t rx, ry;
    float hx = bf16hi_rn(x, rx), hy = bf16hi_rn(y, ry);
    h = __byte_perm(rx, ry, 0x7632);
    l = bf16x2_of(x - hx, y - hy);
}
__device__ __forceinline__ float fast_tanh(float x) {
    float e = __expf(2.f * x);
    return 1.f - __fdividef(2.f, e + 1.f);
}
__device__ __forceinline__ float lk(float v) { return v > 0.f ? v : 0.01f * v; }

__device__ __forceinline__ void stage32(const float* __restrict__ src,
                                        char* Xh, char* Xl, uint32_t off) {
    #pragma unroll
    for (int i = 0; i < 8; ++i) {
        float4 t = reinterpret_cast<const float4*>(src)[i];
        uint32_t r0, r1, r2, r3;
        float h0 = bf16hi_rn(t.x, r0), h1 = bf16hi_rn(t.y, r1);
        float h2 = bf16hi_rn(t.z, r2), h3 = bf16hi_rn(t.w, r3);
        uint2 hh = make_uint2(__byte_perm(r0, r1, 0x7632), __byte_perm(r2, r3, 0x7632));
        uint2 ll = make_uint2(bf16x2_of(t.x - h0, t.y - h1), bf16x2_of(t.z - h2, t.w - h3));
        *reinterpret_cast<uint2*>(Xh + off + i * 8) = hh;
        *reinterpret_cast<uint2*>(Xl + off + i * 8) = ll;
    }
}

// ---------------- core MMA helpers ----------------
// one n-group (n=16): 3-term split using preloaded B frags
__device__ __forceinline__ void mma6(float* acc, const uint32_t* ah, const uint32_t* al,
                                     const uint32_t* bh, const uint32_t* bl) {
    mma_bf16(acc,     ah, bh[0], bh[1]);
    mma_bf16(acc,     ah, bl[0], bl[1]);
    mma_bf16(acc,     al, bh[0], bh[1]);
    mma_bf16(acc + 4, ah, bh[2], bh[3]);
    mma_bf16(acc + 4, ah, bl[2], bl[3]);
    mma_bf16(acc + 4, al, bh[2], bh[3]);
}
// n-group sweep with in-loop LDSM (used where only one A-stream exists)
__device__ __forceinline__ void gemm_groups(float* acc, const uint32_t* ah, const uint32_t* al,
                                            uint32_t baseH, uint32_t baseL, int ngroups)
{
    #pragma unroll
    for (int g = 0; g < 8; ++g) {
        if (g >= ngroups) break;
        uint32_t bh[4], bl[4];
        LDSM4(bh, baseH + g * (16 * ST * 2));
        LDSM4(bl, baseL + g * (16 * ST * 2));
        mma6(acc + 8 * g, ah, al, bh, bl);
    }
}

// ================= prep 1: W1a' = W1a @ P_w, b1' = b1 + W1a @ P_b =================
__global__ void __launch_bounds__(NTH, 1)
ecat_compose(const float* __restrict__ W1, const float* __restrict__ P_w,
             const float* __restrict__ P_b, const float* __restrict__ b1)
{
    int tid = threadIdx.x;
    int o = tid >> 2, jb = (tid & 3) * 32;
    float acc[32];
    #pragma unroll
    for (int j = 0; j < 32; ++j) acc[j] = 0.f;
    for (int i = 0; i < 128; ++i) {
        float w = W1[o * 256 + i];
        const float4* pr = reinterpret_cast<const float4*>(P_w + i * 128 + jb);
        #pragma unroll
        for (int j = 0; j < 8; ++j) {
            float4 p = pr[j];
            acc[4*j]   += w * p.x; acc[4*j+1] += w * p.y;
            acc[4*j+2] += w * p.z; acc[4*j+3] += w * p.w;
        }
    }
    #pragma unroll
    for (int j = 0; j < 8; ++j)
        reinterpret_cast<float4*>(gW1a + o * 128 + jb)[j] =
            make_float4(acc[4*j], acc[4*j+1], acc[4*j+2], acc[4*j+3]);
    if ((tid & 3) == 0) {
        float s = 0.f;
        for (int i = 0; i < 128; ++i) s += W1[o * 256 + i] * P_b[i];
        gB1p[o] = b1[o] + s;
    }
}

// ================= prep 2: weight tiles -> bf16 hi/lo smem images =================
__global__ void __launch_bounds__(NTH, 1)
ecat_convert(const float* __restrict__ W1, const float* __restrict__ W2,
             const float* __restrict__ U_w, const float* __restrict__ V_w)
{
    int b = blockIdx.x;
    int tid = threadIdx.x;
    int o = tid >> 2, qo = (tid & 3) * 32;
    const float* srcRow;
    if (b == 0)      srcRow = gW1a + o * 128 + qo;
    else if (b == 1) srcRow = W1 + o * 256 + 128 + qo;
    else if (b == 2) srcRow = W2 + o * 128 + qo;
    else if (b == 3) srcRow = U_w + (size_t)o * 128 + qo;
    else             srcRow = V_w + (size_t)o * 128 + qo;
    stage32(srcRow, (char*)gWimg[b][0], (char*)gWimg[b][1], (uint32_t)(o * ST + qo) * 2);
}

// ================= prep 3: VU = V@U_w^T, VV = V@V_w^T (persistent, A-in-regs) =================
__global__ void __launch_bounds__(NTH, 1)
ecat_node(const float* __restrict__ V, int n_nodes, int n_ntiles)
{
    extern __shared__ char sm[];
    uint32_t smb = smem_u32(sm);
    const char* gsrc = &gWimg[3][0][0];
    #pragma unroll
    for (int i = 0; i < 17; ++i) {
        int idx = i * NTH + threadIdx.x;
        CP16(smb + idx * 16, gsrc + idx * 16);   // 17*512 = 8704 chunks exactly
    }
    CP_COMMIT(); CP_WAIT();
    __syncthreads();

    const int tid = threadIdx.x, lane = tid & 31, w = tid >> 5;
    const int r0 = lane >> 2, il = lane & 3, cb = il * 2;
    const uint32_t offB = (uint32_t)(((lane & 7) + (((lane >> 4) & 1) << 3)) * ST
                                     + (((lane >> 3) & 1) << 3)) * 2;

    for (int t = blockIdx.x; t < n_ntiles; t += gridDim.x) {
        int n0 = t * 256 + w * 16 + r0;
        int n1 = n0 + 8;
        int n0c = n0 < n_nodes ? n0 : 0;
        int n1c = n1 < n_nodes ? n1 : 0;
        const float2* pa0 = reinterpret_cast<const float2*>(V + (size_t)n0c * 128);
        const float2* pa1 = reinterpret_cast<const float2*>(V + (size_t)n1c * 128);

        #pragma unroll 1
        for (int pass = 0; pass < 2; ++pass) {
            uint32_t bH = smb + pass * 2 * TILEB, bL = bH + TILEB;
            float acc[64];
            #pragma unroll
            for (int i = 0; i < 64; ++i) acc[i] = 0.f;
            #pragma unroll 1
            for (int ks = 0; ks < 8; ++ks) {
                int i0 = il + 8 * ks, i1 = i0 + 4;
                float2 a00 = pa0[i0], a01 = pa0[i1], a10 = pa1[i0], a11 = pa1[i1];
                uint32_t ah[4], al[4];
                split2(a00.x, a00.y, ah[0], al[0]);
                split2(a10.x, a10.y, ah[1], al[1]);
                split2(a01.x, a01.y, ah[2], al[2]);
                split2(a11.x, a11.y, ah[3], al[3]);
                gemm_groups(acc, ah, al, bH + offB + ks * 32, bL + offB + ks * 32, 8);
            }
            float* dstb = pass ? gVV : gVU;
            #pragma unroll
            for (int nf = 0; nf < 16; ++nf) {
                int c = nf * 8 + cb;
                if (n0 < n_nodes)
                    *reinterpret_cast<float2*>(dstb + (size_t)n0 * 128 + c) =
                        make_float2(acc[nf*4], acc[nf*4+1]);
                if (n1 < n_nodes)
                    *reinterpret_cast<float2*>(dstb + (size_t)n1 * 128 + c) =
                        make_float2(acc[nf*4+2], acc[nf*4+3]);
            }
        }
    }
}

// ================= main edge kernel: persistent, merged dual-stream mainloop =================
__global__ void __launch_bounds__(NTH, 1)
ecat_edge(const float* __restrict__ E, const int* __restrict__ src,
          const int* __restrict__ dst, const float* __restrict__ b2,
          float* __restrict__ out, int n_tiles)
{
    extern __shared__ char sm[];
    uint32_t smb = smem_u32(sm);
    const char* gsrc = &gWimg[0][0][0];
    #pragma unroll
    for (int i = 0; i < 26; ++i) {
        int idx = i * NTH + threadIdx.x;
        if (idx < 6 * TILEB / 16) CP16(smb + idx * 16, gsrc + idx * 16);
    }
    CP_COMMIT(); CP_WAIT();
    __syncthreads();

    const int tid = threadIdx.x, lane = tid & 31, w = tid >> 5;
    const int r0 = lane >> 2, il = lane & 3, cb = il * 2;
    const uint32_t offB = (uint32_t)(((lane & 7) + (((lane >> 4) & 1) << 3)) * ST
                                     + (((lane >> 3) & 1) << 3)) * 2;
    const uint32_t uW1aH = smb,             uW1aL = smb + TILEB;
    const uint32_t uW1bH = smb + 2 * TILEB, uW1bL = smb + 3 * TILEB;
    const uint32_t uW2H  = smb + 4 * TILEB, uW2L  = smb + 5 * TILEB;

    for (int t = blockIdx.x; t < n_tiles; t += gridDim.x) {
        long er0 = (long)t * 256 + w * 16 + r0;
        long er1 = er0 + 8;
        int s0 = __ldg(src + er0), s1 = __ldg(src + er1);
        int d0 = __ldg(dst + er0), d1 = __ldg(dst + er1);
        const float2* pu0 = reinterpret_cast<const float2*>(gVU + (size_t)s0 * 128);
        const float2* pu1 = reinterpret_cast<const float2*>(gVU + (size_t)s1 * 128);
        const float2* pv0 = reinterpret_cast<const float2*>(gVV + (size_t)d0 * 128);
        const float2* pv1 = reinterpret_cast<const float2*>(gVV + (size_t)d1 * 128);
        const float2* pe0 = reinterpret_cast<const float2*>(E + er0 * 128);
        const float2* pe1 = reinterpret_cast<const float2*>(E + er1 * 128);

        float acc[64];
        #pragma unroll
        for (int i = 0; i < 64; ++i) acc[i] = 0.f;

        // ---- merged GEMM A+B: two independent LDSM->MMA chains per n-group ----
        #pragma unroll 1
        for (int ks = 0; ks < 8; ++ks) {
            int i0 = il + 8 * ks, i1 = i0 + 4;
            uint32_t ath[4], atl[4], aeh[4], ael[4];
            {
                float2 u00 = pu0[i0], u01 = pu0[i1], u10 = pu1[i0], u11 = pu1[i1];
                float2 v00 = pv0[i0], v01 = pv0[i1], v10 = pv1[i0], v11 = pv1[i1];
                split2(fast_tanh(u00.x * v00.x), fast_tanh(u00.y * v00.y), ath[0], atl[0]);
                split2(fast_tanh(u10.x * v10.x), fast_tanh(u10.y * v10.y), ath[1], atl[1]);
                split2(fast_tanh(u01.x * v01.x), fast_tanh(u01.y * v01.y), ath[2], atl[2]);
                split2(fast_tanh(u11.x * v11.x), fast_tanh(u11.y * v11.y), ath[3], atl[3]);
            }
            {
                float2 e00 = pe0[i0], e01 = pe0[i1], e10 = pe1[i0], e11 = pe1[i1];
                split2(lk(e00.x), lk(e00.y), aeh[0], ael[0]);
                split2(lk(e10.x), lk(e10.y), aeh[1], ael[1]);
                split2(lk(e01.x), lk(e01.y), aeh[2], ael[2]);
                split2(lk(e11.x), lk(e11.y), aeh[3], ael[3]);
            }
            const uint32_t bAH = uW1aH + offB + ks * 32, bAL = uW1aL + offB + ks * 32;
            const uint32_t bBH = uW1bH + offB + ks * 32, bBL = uW1bL + offB + ks * 32;
            #pragma unroll
            for (int g = 0; g < 8; ++g) {
                uint32_t go = (uint32_t)g * (16 * ST * 2);
                uint32_t bha[4], bla[4], bhb[4], blb[4];
                LDSM4(bha, bAH + go);
                LDSM4(bhb, bBH + go);
                LDSM4(bla, bAL + go);
                LDSM4(blb, bBL + go);
                mma6(acc + 8 * g, ath, atl, bha, bla);
                mma6(acc + 8 * g, aeh, ael, bhb, blb);
            }
        }
        // ---- y1 = relu(acc + b1'): repack C-frags directly into GEMM-3 A-frags ----
        uint32_t yh[8][4], yl[8][4];
        #pragma unroll
        for (int ks = 0; ks < 8; ++ks) {
            #pragma unroll
            for (int p = 0; p < 2; ++p) {
                int nf = 2 * ks + p;
                float2 bb = __ldg(reinterpret_cast<const float2*>(gB1p + nf * 8 + cb));
                float y0 = fmaxf(acc[nf*4+0] + bb.x, 0.f);
                float y1v = fmaxf(acc[nf*4+1] + bb.y, 0.f);
                float y2 = fmaxf(acc[nf*4+2] + bb.x, 0.f);
                float y3 = fmaxf(acc[nf*4+3] + bb.y, 0.f);
                split2(y0, y1v, yh[ks][2*p],     yl[ks][2*p]);
                split2(y2, y3,  yh[ks][2*p + 1], yl[ks][2*p + 1]);
            }
        }
        // ---- GEMM C: out = relu(y1 @ W2^T + b2), n processed in halves ----
        #pragma unroll 1
        for (int h = 0; h < 2; ++h) {
            float acc2[32];
            #pragma unroll
            for (int i = 0; i < 32; ++i) acc2[i] = 0.f;
            uint32_t hb = (uint32_t)h * (64 * ST * 2);
            #pragma unroll 1
            for (int ks = 0; ks < 8; ++ks)
                gemm_groups(acc2, yh[ks], yl[ks],
                            uW2H + offB + hb + ks * 32, uW2L + offB + hb + ks * 32, 4);
            #pragma unroll
            for (int nf = 0; nf < 8; ++nf) {
                int c = h * 64 + nf * 8 + cb;
                float2 bb = __ldg(reinterpret_cast<const float2*>(b2 + c));
                *reinterpret_cast<float2*>(out + er0 * 128 + c) =
                    make_float2(fmaxf(acc2[nf*4+0] + bb.x, 0.f),
                                fmaxf(acc2[nf*4+1] + bb.y, 0.f));
                *reinterpret_cast<float2*>(out + er1 * 128 + c) =
                    make_float2(fmaxf(acc2[nf*4+2] + bb.x, 0.f),
                                fmaxf(acc2[nf*4+3] + bb.y, 0.f));
            }
        }
    }
}

// ================= host =================
extern "C" void kernel_launch(void* const* d_in, const int* in_sizes, int n_in,
                              void* d_out, int out_size)
{
    const float* V   = (const float*)d_in[0];
    const float* E   = (const float*)d_in[1];
    const int*   src = (const int*)d_in[2];
    const int*   dst = (const int*)d_in[3];
    const float* U_w = (const float*)d_in[4];
    const float* V_w = (const float*)d_in[5];
    const float* P_w = (const float*)d_in[6];
    const float* P_b = (const float*)d_in[7];
    const float* W1  = (const float*)d_in[8];
    const float* b1  = (const float*)d_in[9];
    const float* W2  = (const float*)d_in[10];
    const float* b2  = (const float*)d_in[11];
    float* out = (float*)d_out;

    int n_nodes = in_sizes[0] / 128;
    int n_edges = in_sizes[2];
    int n_tiles = n_edges / 256;                 // 2500
    int n_ntiles = (n_nodes + 255) / 256;        // 391

    static int sms = 0;
    if (!sms) {
        cudaDeviceGetAttribute(&sms, cudaDevAttrMultiProcessorCount, 0);
        cudaFuncSetAttribute(ecat_node, cudaFuncAttributeMaxDynamicSharedMemorySize, NODE_SMEM);
        cudaFuncSetAttribute(ecat_edge, cudaFuncAttributeMaxDynamicSharedMemorySize, EDGE_SMEM);
    }

    ecat_compose<<<1, NTH>>>(W1, P_w, P_b, b1);
    ecat_convert<<<5, NTH>>>(W1, W2, U_w, V_w);
    ecat_node<<<sms, NTH, NODE_SMEM>>>(V, n_nodes, n_ntiles);
    ecat_edge<<<sms, NTH, EDGE_SMEM>>>(E, src, dst, b2, out, n_tiles);
}